// round 13
// baseline (speedup 1.0000x reference)
#include <cuda_runtime.h>
#include <math.h>

#define BATCH 8192
#define CONV_OUT 5104      // 8 * 22 * 29
#define KHALF 2552         // CONV_OUT / 2 (K-split across blockIdx.y)
#define SSZ 32
#define NSZ 19
#define UNFOLDS 6
#define L2E 1.4426950408889634f

#define CHUNK 8            // outputs per scan CTA
#define NCHUNK (BATCH / CHUNK)   // 1024 CTAs
#define WARMUP 48          // discarded convergence steps before each chunk

// ---------------- static scratch (no allocations allowed) ----------------
__device__ float g_act[(size_t)BATCH * CONV_OUT];   // conv+ELU output, 167 MB
__device__ float g_hp0[BATCH * 64];                 // fc1 partial sums (K-half 0)
__device__ float g_hp1[BATCH * 64];                 // fc1 partial sums (K-half 1)
__device__ float2 g_sens2[BATCH * 32];              // [t][lane] = (wnum_s + g*vleak, wden_s)
// transformed recurrent params for tanh form, [src][32] stride-32 padded
__device__ float g_rP[NSZ * 32], g_rQ[NSZ * 32], g_rA[NSZ * 32], g_rW[NSZ * 32];
__device__ float g_cmt[32], g_cg2[32], g_gvl[32], g_hA[32];
// transformed sensory params (sigmoid ex2 form), [s][n] stride NSZ
__device__ float g_sP[SSZ * NSZ], g_sQ[SSZ * NSZ], g_sA[SSZ * NSZ], g_sW[SSZ * NSZ];

__device__ __forceinline__ float fast_ex2(float x) {
    float y; asm("ex2.approx.f32 %0, %1;" : "=f"(y) : "f"(x)); return y;
}
__device__ __forceinline__ float fast_rcp(float x) {
    float y; asm("rcp.approx.f32 %0, %1;" : "=f"(y) : "f"(x)); return y;
}
__device__ __forceinline__ float fast_tanh(float x) {
    float y; asm("tanh.approx.f32 %0, %1;" : "=f"(y) : "f"(x)); return y;
}
// tf32 split: x = hi + lo, both representable in tf32 (error ~ eps^2)
__device__ __forceinline__ void split_tf32(float x, unsigned& hi, unsigned& lo) {
    asm("cvt.rna.tf32.f32 %0, %1;" : "=r"(hi) : "f"(x));
    float l = x - __uint_as_float(hi);
    asm("cvt.rna.tf32.f32 %0, %1;" : "=r"(lo) : "f"(l));
}
__device__ __forceinline__ void mma_tf32(float* c, const unsigned* a, unsigned b0, unsigned b1) {
    asm volatile(
        "mma.sync.aligned.m16n8k8.row.col.f32.tf32.tf32.f32 "
        "{%0,%1,%2,%3}, {%4,%5,%6,%7}, {%8,%9}, {%0,%1,%2,%3};"
        : "+f"(c[0]), "+f"(c[1]), "+f"(c[2]), "+f"(c[3])
        : "r"(a[0]), "r"(a[1]), "r"(a[2]), "r"(a[3]), "r"(b0), "r"(b1));
}

// ---------------- K0: parameter transforms (runs once per launch) ----------------
__global__ void k_prep(const float* __restrict__ w,     const float* __restrict__ mu,
                       const float* __restrict__ sigma, const float* __restrict__ erev,
                       const float* __restrict__ mask,
                       const float* __restrict__ gleak, const float* __restrict__ vleak,
                       const float* __restrict__ cm,
                       const float* __restrict__ sw,    const float* __restrict__ smu,
                       const float* __restrict__ ssig,  const float* __restrict__ serev,
                       const float* __restrict__ smask) {
    int i = threadIdx.x;
    if (i < NSZ * NSZ) {
        int s = i / NSZ, n = i % NSZ;
        float wp = log1pf(expf(w[i])) * mask[i];     // softplus(w) * mask
        // sigmoid(sigma*(v-mu)) = 0.5 + 0.5*tanh(0.5*sigma*(v-mu))
        g_rP[s * 32 + n] =  0.5f * sigma[i];
        g_rQ[s * 32 + n] = -0.5f * sigma[i] * mu[i];
        g_rA[s * 32 + n] =  0.5f * wp * erev[i];     // coefficient of tanh in numerator
        g_rW[s * 32 + n] =  0.5f * wp;               // coefficient of tanh in denominator
    }
    if (i < SSZ * NSZ) {
        float sp = log1pf(expf(sw[i])) * smask[i];
        g_sP[i] = -ssig[i] * L2E;
        g_sQ[i] =  ssig[i] * smu[i] * L2E;
        g_sA[i] =  sp * serev[i];
        g_sW[i] =  sp;
    }
    __syncthreads();
    if (i < NSZ) {
        float g   = log1pf(expf(gleak[i]));
        float cmt = log1pf(expf(cm[i])) * (float)UNFOLDS;
        float sumA = 0.f, sumW = 0.f;
        for (int s = 0; s < NSZ; s++) { sumA += g_rA[s * 32 + i]; sumW += g_rW[s * 32 + i]; }
        g_cmt[i] = cmt;
        g_cg2[i] = cmt + g + 1e-8f + sumW;           // denom const (+EPS +0.5*sum wp)
        g_gvl[i] = g * vleak[i];                     // numerator constant part
        g_hA[i]  = sumA;                             // numerator constant: 0.5*sum(wp*erev)
    }
}

// ---------------- K1: conv 2x2 VALID + fast ELU, flattened NCHW ----------------
// 4 consecutive outputs per thread, single STG.128 (5104 = 1276*4 exactly).
__global__ void k_conv(const float* __restrict__ x, const float* __restrict__ cw,
                       const float* __restrict__ cb) {
    __shared__ float sx[3 * 23 * 30];   // 2070
    __shared__ float swt[96];
    __shared__ float sb[8];
    int b = blockIdx.x;
    const float* xb = x + (size_t)b * 2070;
    for (int i = threadIdx.x; i < 2070; i += blockDim.x) sx[i] = xb[i];
    if (threadIdx.x < 96) swt[threadIdx.x] = cw[threadIdx.x];
    if (threadIdx.x < 8)  sb[threadIdx.x] = cb[threadIdx.x];
    __syncthreads();
    float* ob = g_act + (size_t)b * CONV_OUT;
    for (int o4 = threadIdx.x; o4 < CONV_OUT / 4; o4 += blockDim.x) {
        int ob0 = o4 * 4;
        float res[4];
        #pragma unroll
        for (int e = 0; e < 4; e++) {
            int o = ob0 + e;
            int c = o / 638;          // 22*29
            int r = o % 638;
            int i = r / 29, j = r % 29;
            float acc = sb[c];
            #pragma unroll
            for (int ci = 0; ci < 3; ci++)
                #pragma unroll
                for (int ki = 0; ki < 2; ki++)
                    #pragma unroll
                    for (int kj = 0; kj < 2; kj++)
                        acc = fmaf(sx[ci * 690 + (i + ki) * 30 + (j + kj)],
                                   swt[c * 12 + ci * 4 + ki * 2 + kj], acc);
            // ELU: expm1 via ex2.approx (3 instr vs ~15 for expm1f)
            res[e] = acc > 0.f ? acc : fast_ex2(acc * L2E) - 1.0f;
        }
        *(float4*)(ob + ob0) = make_float4(res[0], res[1], res[2], res[3]);
    }
}

// ---------------- K2: FC1 GEMM (8192x64, K=5104) via 3xTF32 mma.sync, K-SPLIT ----
// R9's winning inner tile (M=64, 8 warps 4(M)x2(N), warp m16n32, 48 MMA : 48 split);
// K split in half across blockIdx.y -> grid (128,2) = 256 CTAs.
#define KT 32
#define KITER_H ((KHALF + KT - 1) / KT)    // 80 (last tile 24 valid, zero-padded)
__global__ void __launch_bounds__(256, 2)
k_fc1(const float* __restrict__ fw) {
    __shared__ float As[KT][72];      // [k][m]; stride 72 -> frag LDS conflict-free
    __shared__ float Bs[KT][72];      // [k][n]
    int tid = threadIdx.x;
    int block_m = blockIdx.x * 64;
    int kbeg = blockIdx.y * KHALF;    // this CTA's K-half origin
    float* hp = blockIdx.y ? g_hp1 : g_hp0;
    int warp = tid >> 5, lane = tid & 31;
    int wm = (warp & 3) * 16;         // warp m-offset
    int wn = (warp >> 2) * 32;        // warp n-offset
    int g = lane >> 2, tg = lane & 3;
    // loader mapping: p in [0,512): row=p>>3 (0..63), f4=(p&7)*4 (k-offset)
    int p0 = tid, p1 = tid + 256;
    int lrow0 = p0 >> 3, lf0 = (p0 & 7) * 4;
    int lrow1 = p1 >> 3, lf1 = (p1 & 7) * 4;
    const float* aptr0 = g_act + (size_t)(block_m + lrow0) * CONV_OUT + kbeg + lf0;
    const float* aptr1 = g_act + (size_t)(block_m + lrow1) * CONV_OUT + kbeg + lf1;
    const float* bptr0 = fw + (size_t)lrow0 * CONV_OUT + kbeg + lf0;
    const float* bptr1 = fw + (size_t)lrow1 * CONV_OUT + kbeg + lf1;
    const float4 z4 = make_float4(0.f, 0.f, 0.f, 0.f);

    float c[4][4];                    // 4 n-subtiles x 4 accum regs
    #pragma unroll
    for (int j = 0; j < 4; j++)
        #pragma unroll
        for (int i = 0; i < 4; i++) c[j][i] = 0.f;

    // initial prefetch (local k0 = 0; always in range)
    float4 a0 = *(const float4*)(aptr0);
    float4 a1 = *(const float4*)(aptr1);
    float4 b0 = *(const float4*)(bptr0);
    float4 b1 = *(const float4*)(bptr1);

    #pragma unroll 1
    for (int it = 0; it < KITER_H; it++) {
        As[lf0 + 0][lrow0] = a0.x; As[lf0 + 1][lrow0] = a0.y;
        As[lf0 + 2][lrow0] = a0.z; As[lf0 + 3][lrow0] = a0.w;
        As[lf1 + 0][lrow1] = a1.x; As[lf1 + 1][lrow1] = a1.y;
        As[lf1 + 2][lrow1] = a1.z; As[lf1 + 3][lrow1] = a1.w;
        Bs[lf0 + 0][lrow0] = b0.x; Bs[lf0 + 1][lrow0] = b0.y;
        Bs[lf0 + 2][lrow0] = b0.z; Bs[lf0 + 3][lrow0] = b0.w;
        Bs[lf1 + 0][lrow1] = b1.x; Bs[lf1 + 1][lrow1] = b1.y;
        Bs[lf1 + 2][lrow1] = b1.z; Bs[lf1 + 3][lrow1] = b1.w;
        __syncthreads();
        // prefetch next K-block (overlaps with compute); zero-pad the half's tail
        int nk = (it + 1) * KT;
        if (it + 1 < KITER_H) {
            bool v0 = (nk + lf0) < KHALF;
            bool v1 = (nk + lf1) < KHALF;
            a0 = v0 ? *(const float4*)(aptr0 + nk) : z4;
            a1 = v1 ? *(const float4*)(aptr1 + nk) : z4;
            b0 = v0 ? *(const float4*)(bptr0 + nk) : z4;
            b1 = v1 ? *(const float4*)(bptr1 + nk) : z4;
        }
        #pragma unroll
        for (int kk = 0; kk < KT; kk += 8) {
            // A fragment m16k8: a0=(g,tg) a1=(g+8,tg) a2=(g,tg+4) a3=(g+8,tg+4)
            unsigned ah[4], al[4];
            split_tf32(As[kk + tg][wm + g],          ah[0], al[0]);
            split_tf32(As[kk + tg][wm + g + 8],      ah[1], al[1]);
            split_tf32(As[kk + tg + 4][wm + g],      ah[2], al[2]);
            split_tf32(As[kk + tg + 4][wm + g + 8],  ah[3], al[3]);
            #pragma unroll
            for (int j = 0; j < 4; j++) {
                // B fragment k8n8 (col): b0=(tg,g) b1=(tg+4,g)
                unsigned bh0, bl0, bh1, bl1;
                split_tf32(Bs[kk + tg][wn + j * 8 + g],     bh0, bl0);
                split_tf32(Bs[kk + tg + 4][wn + j * 8 + g], bh1, bl1);
                mma_tf32(c[j], ah, bh0, bh1);     // hi*hi
                mma_tf32(c[j], al, bh0, bh1);     // lo*hi
                mma_tf32(c[j], ah, bl0, bl1);     // hi*lo
            }
        }
        __syncthreads();
    }
    // epilogue: raw partial sums (bias+relu applied in k_sens after combine)
    #pragma unroll
    for (int j = 0; j < 4; j++) {
        int n = wn + j * 8 + tg * 2;
        int r0 = block_m + wm + g;
        float2 lo = make_float2(c[j][0], c[j][1]);
        float2 hi = make_float2(c[j][2], c[j][3]);
        *(float2*)&hp[r0 * 64 + n] = lo;
        *(float2*)&hp[(r0 + 8) * 64 + n] = hi;
    }
}

// ---------------- K3: combine fc1 halves + bias + relu, FC2, input-affine,
//                     sensory synapse sums ----------------
__global__ void k_sens(const float* __restrict__ fc1b,
                       const float* __restrict__ fc2w, const float* __restrict__ fc2b,
                       const float* __restrict__ inw,  const float* __restrict__ inb) {
    __shared__ float ws[64][32];       // ws[o][j] = fc2w[j*64+o]
    __shared__ float sh_h[8][64];
    __shared__ float sh_seq[8][33];
    int tid = threadIdx.x, warp = tid >> 5, lane = tid & 31;
    for (int i = tid; i < 2048; i += 256) ws[i & 63][i >> 6] = fc2w[i];  // coalesced LDG
    int t = blockIdx.x * 8 + warp;
    float h0 = g_hp0[t * 64 + lane]      + g_hp1[t * 64 + lane]      + fc1b[lane];
    float h1 = g_hp0[t * 64 + 32 + lane] + g_hp1[t * 64 + 32 + lane] + fc1b[32 + lane];
    h0 = h0 > 0.f ? h0 : 0.f;          // relu after deterministic combine
    h1 = h1 > 0.f ? h1 : 0.f;
    sh_h[warp][lane] = h0;
    sh_h[warp][32 + lane] = h1;
    __syncthreads();                                  // ws + sh_h visible
    float y0 = fc2b[lane], y1 = 0.f, y2 = 0.f, y3 = 0.f;  // 4-way split chains
    #pragma unroll
    for (int o = 0; o < 64; o += 4) {
        y0 = fmaf(ws[o + 0][lane], sh_h[warp][o + 0], y0);
        y1 = fmaf(ws[o + 1][lane], sh_h[warp][o + 1], y1);
        y2 = fmaf(ws[o + 2][lane], sh_h[warp][o + 2], y2);
        y3 = fmaf(ws[o + 3][lane], sh_h[warp][o + 3], y3);
    }
    float y = (y0 + y1) + (y2 + y3);
    float seq = fmaf(y, inw[lane], inb[lane]);
    sh_seq[warp][lane] = seq;
    __syncwarp();
    if (lane < NSZ) {
        float wn0 = 0.f, wn1 = 0.f, wd0 = 0.f, wd1 = 0.f;   // 2-way split MUFU chains
        #pragma unroll
        for (int s = 0; s < SSZ; s += 2) {
            float arg0 = fmaf(g_sP[s * NSZ + lane], sh_seq[warp][s], g_sQ[s * NSZ + lane]);
            float arg1 = fmaf(g_sP[(s + 1) * NSZ + lane], sh_seq[warp][s + 1],
                              g_sQ[(s + 1) * NSZ + lane]);
            float r0 = fast_rcp(1.0f + fast_ex2(arg0));
            float r1 = fast_rcp(1.0f + fast_ex2(arg1));
            wn0 = fmaf(g_sA[s * NSZ + lane], r0, wn0);
            wd0 = fmaf(g_sW[s * NSZ + lane], r0, wd0);
            wn1 = fmaf(g_sA[(s + 1) * NSZ + lane], r1, wn1);
            wd1 = fmaf(g_sW[(s + 1) * NSZ + lane], r1, wd1);
        }
        g_sens2[t * 32 + lane] = make_float2((wn0 + wn1) + g_gvl[lane], wd0 + wd1);
    }
}

// ---------------- K4: parallel-in-time LTC scan.
// CHUNK=8 outputs/CTA (1024 CTAs, all resident), WARMUP=48 discarded steps
// (worst-case contraction 0.82^48 ~ 7e-5; empirically far stronger). Chunk 0 exact.
__global__ void __launch_bounds__(128, 1)
k_scan(float* __restrict__ out, const float* __restrict__ ow,
       const float* __restrict__ ob) {
    __shared__ float2 s_p[2][4][32];                  // packed (wn, wd) partials
    int tid = threadIdx.x, w = tid >> 5, lane = tid & 31;
    int w1 = (w + 1) & 3, w2 = (w + 2) & 3, w3 = (w + 3) & 3;
    bool act = lane < NSZ;
    float P[5], Q[5], A[5], W[5];
    int srcl[5];
    #pragma unroll
    for (int cc = 0; cc < 5; cc++) {
        int s = w * 5 + cc;
        bool ok = act && (s < NSZ);
        srcl[cc] = s < NSZ ? s : 0;
        P[cc] = ok ? g_rP[s * 32 + lane] : 0.f;
        Q[cc] = ok ? g_rQ[s * 32 + lane] : 0.f;
        A[cc] = ok ? g_rA[s * 32 + lane] : 0.f;
        W[cc] = ok ? g_rW[s * 32 + lane] : 0.f;
    }
    float cmt = act ? g_cmt[lane] : 0.f;
    float cg2 = act ? g_cg2[lane] : 1.f;
    float hA  = act ? g_hA[lane]  : 0.f;
    float ow0 = ow[0], ob0 = ob[0];

    int tbeg = blockIdx.x * CHUNK;
    int t0   = tbeg - WARMUP; if (t0 < 0) t0 = 0;
    int tend = tbeg + CHUNK;

    float v = 0.f;
    float2 sb = g_sens2[t0 * 32 + lane];
    for (int t = t0; t < tend; t++) {
        float2 nx = g_sens2[((t + 1) & (BATCH - 1)) * 32 + lane];
        float wn_base = sb.x + hA;
        float wd_base = sb.y + cg2;
        #pragma unroll
        for (int u = 0; u < UNFOLDS; u++) {
            float vv0 = __shfl_sync(0xffffffffu, v, srcl[0]);
            float vv1 = __shfl_sync(0xffffffffu, v, srcl[1]);
            float vv2 = __shfl_sync(0xffffffffu, v, srcl[2]);
            float vv3 = __shfl_sync(0xffffffffu, v, srcl[3]);
            float vv4 = __shfl_sync(0xffffffffu, v, srcl[4]);
            float t_0 = fast_tanh(fmaf(P[0], vv0, Q[0]));
            float t_1 = fast_tanh(fmaf(P[1], vv1, Q[1]));
            float t_2 = fast_tanh(fmaf(P[2], vv2, Q[2]));
            float t_3 = fast_tanh(fmaf(P[3], vv3, Q[3]));
            float t_4 = fast_tanh(fmaf(P[4], vv4, Q[4]));
            float pn = fmaf(A[4], t_4, fmaf(A[0], t_0, A[2] * t_2) + fmaf(A[1], t_1, A[3] * t_3));
            float pd = fmaf(W[4], t_4, fmaf(W[0], t_0, W[2] * t_2) + fmaf(W[1], t_1, W[3] * t_3));
            s_p[u & 1][w][lane] = make_float2(pn, pd);
            float wn_own = wn_base + pn;
            float wd_own = wd_base + pd;
            __syncthreads();
            float2 o1 = s_p[u & 1][w1][lane];
            float2 o2 = s_p[u & 1][w2][lane];
            float2 o3 = s_p[u & 1][w3][lane];
            float wn = (wn_own + o1.x) + (o2.x + o3.x);
            float wd = (wd_own + o1.y) + (o2.y + o3.y);
            v = fmaf(cmt, v, wn) * fast_rcp(wd);
        }
        if (tid == 96 && t >= tbeg) out[t] = fmaf(v, ow0, ob0);
        sb = nx;
    }
}

// ---------------- launch ----------------
extern "C" void kernel_launch(void* const* d_in, const int* in_sizes, int n_in,
                              void* d_out, int out_size) {
    const float* x        = (const float*)d_in[0];
    const float* conv_w   = (const float*)d_in[1];
    const float* conv_b   = (const float*)d_in[2];
    const float* fc1_w    = (const float*)d_in[3];
    const float* fc1_b    = (const float*)d_in[4];
    const float* fc2_w    = (const float*)d_in[5];
    const float* fc2_b    = (const float*)d_in[6];
    const float* input_w  = (const float*)d_in[7];
    const float* input_b  = (const float*)d_in[8];
    const float* s_w      = (const float*)d_in[9];
    const float* s_mu     = (const float*)d_in[10];
    const float* s_sigma  = (const float*)d_in[11];
    const float* s_erev   = (const float*)d_in[12];
    const float* s_mask   = (const float*)d_in[13];
    const float* w        = (const float*)d_in[14];
    const float* mu       = (const float*)d_in[15];
    const float* sigma    = (const float*)d_in[16];
    const float* erev     = (const float*)d_in[17];
    const float* mask     = (const float*)d_in[18];
    const float* gleak    = (const float*)d_in[19];
    const float* vleak    = (const float*)d_in[20];
    const float* cm       = (const float*)d_in[21];
    const float* output_w = (const float*)d_in[22];
    const float* output_b = (const float*)d_in[23];

    k_prep<<<1, 640>>>(w, mu, sigma, erev, mask, gleak, vleak, cm,
                       s_w, s_mu, s_sigma, s_erev, s_mask);
    k_conv<<<BATCH, 256>>>(x, conv_w, conv_b);
    dim3 fc1_grid(BATCH / 64, 2);
    k_fc1<<<fc1_grid, 256>>>(fc1_w);
    k_sens<<<BATCH / 8, 256>>>(fc1_b, fc2_w, fc2_b, input_w, input_b);
    k_scan<<<NCHUNK, 128>>>((float*)d_out, output_w, output_b);
}

// round 15
// speedup vs baseline: 1.1784x; 1.1784x over previous
#include <cuda_runtime.h>
#include <math.h>

#define BATCH 8192
#define CONV_OUT 5104      // 8 * 22 * 29
#define KHALF 2552         // CONV_OUT / 2 (K-split across blockIdx.y)
#define SSZ 32
#define NSZ 19
#define UNFOLDS 6
#define L2E 1.4426950408889634f

#define CHUNK 16           // outputs per scan CTA
#define NCHUNK (BATCH / CHUNK)   // 512 CTAs
#define WARMUP 56          // discarded convergence steps before each chunk

// ---------------- static scratch (no allocations allowed) ----------------
__device__ float g_act[(size_t)BATCH * CONV_OUT];   // conv+ELU output, 167 MB
__device__ float g_hp0[BATCH * 64];                 // fc1 partial sums (K-half 0)
__device__ float g_hp1[BATCH * 64];                 // fc1 partial sums (K-half 1)
__device__ float2 g_sens2[BATCH * 32];              // [t][lane] = (wnum_s + g*vleak, wden_s)
// transformed recurrent params for tanh form, [src][32] stride-32 padded
__device__ float g_rP[NSZ * 32], g_rQ[NSZ * 32], g_rA[NSZ * 32], g_rW[NSZ * 32];
__device__ float g_cmt[32], g_cg2[32], g_gvl[32], g_hA[32];
// transformed sensory params (sigmoid ex2 form), [s][n] stride NSZ
__device__ float g_sP[SSZ * NSZ], g_sQ[SSZ * NSZ], g_sA[SSZ * NSZ], g_sW[SSZ * NSZ];

__device__ __forceinline__ float fast_ex2(float x) {
    float y; asm("ex2.approx.f32 %0, %1;" : "=f"(y) : "f"(x)); return y;
}
__device__ __forceinline__ float fast_rcp(float x) {
    float y; asm("rcp.approx.f32 %0, %1;" : "=f"(y) : "f"(x)); return y;
}
__device__ __forceinline__ float fast_tanh(float x) {
    float y; asm("tanh.approx.f32 %0, %1;" : "=f"(y) : "f"(x)); return y;
}
// tf32 split: x = hi + lo, both representable in tf32 (error ~ eps^2)
__device__ __forceinline__ void split_tf32(float x, unsigned& hi, unsigned& lo) {
    asm("cvt.rna.tf32.f32 %0, %1;" : "=r"(hi) : "f"(x));
    float l = x - __uint_as_float(hi);
    asm("cvt.rna.tf32.f32 %0, %1;" : "=r"(lo) : "f"(l));
}
__device__ __forceinline__ void mma_tf32(float* c, const unsigned* a, unsigned b0, unsigned b1) {
    asm volatile(
        "mma.sync.aligned.m16n8k8.row.col.f32.tf32.tf32.f32 "
        "{%0,%1,%2,%3}, {%4,%5,%6,%7}, {%8,%9}, {%0,%1,%2,%3};"
        : "+f"(c[0]), "+f"(c[1]), "+f"(c[2]), "+f"(c[3])
        : "r"(a[0]), "r"(a[1]), "r"(a[2]), "r"(a[3]), "r"(b0), "r"(b1));
}
__device__ __forceinline__ void cp_async16(void* smem, const void* gmem, int src_bytes) {
    unsigned saddr = (unsigned)__cvta_generic_to_shared(smem);
    asm volatile("cp.async.ca.shared.global [%0], [%1], 16, %2;"
                 :: "r"(saddr), "l"(gmem), "r"(src_bytes));
}
#define CP_COMMIT() asm volatile("cp.async.commit_group;")
#define CP_WAIT2()  asm volatile("cp.async.wait_group 2;")

// ---------------- K0: parameter transforms (runs once per launch) ----------------
__global__ void k_prep(const float* __restrict__ w,     const float* __restrict__ mu,
                       const float* __restrict__ sigma, const float* __restrict__ erev,
                       const float* __restrict__ mask,
                       const float* __restrict__ gleak, const float* __restrict__ vleak,
                       const float* __restrict__ cm,
                       const float* __restrict__ sw,    const float* __restrict__ smu,
                       const float* __restrict__ ssig,  const float* __restrict__ serev,
                       const float* __restrict__ smask) {
    int i = threadIdx.x;
    if (i < NSZ * NSZ) {
        int s = i / NSZ, n = i % NSZ;
        float wp = log1pf(expf(w[i])) * mask[i];     // softplus(w) * mask
        // sigmoid(sigma*(v-mu)) = 0.5 + 0.5*tanh(0.5*sigma*(v-mu))
        g_rP[s * 32 + n] =  0.5f * sigma[i];
        g_rQ[s * 32 + n] = -0.5f * sigma[i] * mu[i];
        g_rA[s * 32 + n] =  0.5f * wp * erev[i];     // coefficient of tanh in numerator
        g_rW[s * 32 + n] =  0.5f * wp;               // coefficient of tanh in denominator
    }
    if (i < SSZ * NSZ) {
        float sp = log1pf(expf(sw[i])) * smask[i];
        g_sP[i] = -ssig[i] * L2E;
        g_sQ[i] =  ssig[i] * smu[i] * L2E;
        g_sA[i] =  sp * serev[i];
        g_sW[i] =  sp;
    }
    __syncthreads();
    if (i < NSZ) {
        float g   = log1pf(expf(gleak[i]));
        float cmt = log1pf(expf(cm[i])) * (float)UNFOLDS;
        float sumA = 0.f, sumW = 0.f;
        for (int s = 0; s < NSZ; s++) { sumA += g_rA[s * 32 + i]; sumW += g_rW[s * 32 + i]; }
        g_cmt[i] = cmt;
        g_cg2[i] = cmt + g + 1e-8f + sumW;           // denom const (+EPS +0.5*sum wp)
        g_gvl[i] = g * vleak[i];                     // numerator constant part
        g_hA[i]  = sumA;                             // numerator constant: 0.5*sum(wp*erev)
    }
}

// ---------------- K1: conv 2x2 VALID + fast ELU, flattened NCHW ----------------
__global__ void k_conv(const float* __restrict__ x, const float* __restrict__ cw,
                       const float* __restrict__ cb) {
    __shared__ float sx[3 * 23 * 30];   // 2070
    __shared__ float swt[96];
    __shared__ float sb[8];
    int b = blockIdx.x;
    const float* xb = x + (size_t)b * 2070;
    for (int i = threadIdx.x; i < 2070; i += blockDim.x) sx[i] = xb[i];
    if (threadIdx.x < 96) swt[threadIdx.x] = cw[threadIdx.x];
    if (threadIdx.x < 8)  sb[threadIdx.x] = cb[threadIdx.x];
    __syncthreads();
    float* ob = g_act + (size_t)b * CONV_OUT;
    for (int o = threadIdx.x; o < CONV_OUT; o += blockDim.x) {
        int c = o / 638;          // 22*29
        int r = o % 638;
        int i = r / 29, j = r % 29;
        float acc = sb[c];
        #pragma unroll
        for (int ci = 0; ci < 3; ci++)
            #pragma unroll
            for (int ki = 0; ki < 2; ki++)
                #pragma unroll
                for (int kj = 0; kj < 2; kj++)
                    acc = fmaf(sx[ci * 690 + (i + ki) * 30 + (j + kj)],
                               swt[c * 12 + ci * 4 + ki * 2 + kj], acc);
        // ELU: expm1 via ex2.approx (3 instr vs ~15 for expm1f)
        ob[o] = acc > 0.f ? acc : fast_ex2(acc * L2E) - 1.0f;
    }
}

// ---------------- K2: FC1 GEMM (8192x64, K=5104), 3xTF32 mma.sync, K-SPLIT,
// 4-stage cp.async pipeline (R10 ncu: register-prefetch version was ~8x stalled
// at 4200 cyc/tile; 3 tiles in flight cover DRAM latency). ----------------
#define KT 16
#define STAGES 4
#define KITER_H ((KHALF + KT - 1) / KT)    // 160 (last tile 8 valid, zero-filled)
__global__ void __launch_bounds__(256, 2)
k_fc1(const float* __restrict__ fw) {
    // row-major smem [row][k], stride 20: fragment LDS bank = (row*20+k) mod 32
    // is a perfect 32-permutation over (8 rows x 4 k) -> conflict-free.
    __shared__ float As[STAGES][64][20];   // 20,480 B
    __shared__ float Bs[STAGES][64][20];   // 20,480 B  (total 40 KB < 48 KB static)
    int tid = threadIdx.x;
    int block_m = blockIdx.x * 64;
    int kbeg = blockIdx.y * KHALF;
    float* hp = blockIdx.y ? g_hp1 : g_hp0;
    int warp = tid >> 5, lane = tid & 31;
    int wm = (warp & 3) * 16;         // warp m-offset
    int wn = (warp >> 2) * 32;        // warp n-offset
    int g = lane >> 2, tg = lane & 3;
    // loader: thread -> one 16B chunk of A and one of B per tile
    int lrow = tid >> 2;              // 0..63
    int lk4  = (tid & 3) * 4;         // 0,4,8,12
    const float* abase = g_act + (size_t)(block_m + lrow) * CONV_OUT + kbeg;
    const float* bbase = fw + (size_t)lrow * CONV_OUT + kbeg;

    float c[4][4], d[4][4];           // dual accumulators (hi*hi | corrections)
    #pragma unroll
    for (int j = 0; j < 4; j++)
        #pragma unroll
        for (int i = 0; i < 4; i++) { c[j][i] = 0.f; d[j][i] = 0.f; }

    // prologue: stages for tiles 0..2 (16B chunks always aligned; tail zero-fills)
    #pragma unroll
    for (int it = 0; it < STAGES - 1; it++) {
        int kl = it * KT + lk4;
        int sbytes = kl < KHALF ? 16 : 0;
        int kcl = kl < KHALF ? kl : 0;
        cp_async16(&As[it][lrow][lk4], abase + kcl, sbytes);
        cp_async16(&Bs[it][lrow][lk4], bbase + kcl, sbytes);
        CP_COMMIT();
    }

    #pragma unroll 1
    for (int it = 0; it < KITER_H; it++) {
        CP_WAIT2();                   // tile it's group retired (uniform 1 commit/iter)
        __syncthreads();              // also guards buffer reuse: all warps past it-1
        int nt = it + STAGES - 1;
        if (nt < KITER_H) {
            int s = nt & (STAGES - 1);
            int kl = nt * KT + lk4;
            int sbytes = kl < KHALF ? 16 : 0;
            int kcl = kl < KHALF ? kl : 0;
            cp_async16(&As[s][lrow][lk4], abase + kcl, sbytes);
            cp_async16(&Bs[s][lrow][lk4], bbase + kcl, sbytes);
        }
        CP_COMMIT();                  // unconditional: keeps group accounting exact
        int s = it & (STAGES - 1);
        #pragma unroll
        for (int kk = 0; kk < KT; kk += 8) {
            // A fragment m16k8: (g,tg) (g+8,tg) (g,tg+4) (g+8,tg+4)
            unsigned ah[4], al[4];
            split_tf32(As[s][wm + g][kk + tg],          ah[0], al[0]);
            split_tf32(As[s][wm + g + 8][kk + tg],      ah[1], al[1]);
            split_tf32(As[s][wm + g][kk + tg + 4],      ah[2], al[2]);
            split_tf32(As[s][wm + g + 8][kk + tg + 4],  ah[3], al[3]);
            #pragma unroll
            for (int j = 0; j < 4; j++) {
                unsigned bh0, bl0, bh1, bl1;
                split_tf32(Bs[s][wn + j * 8 + g][kk + tg],     bh0, bl0);
                split_tf32(Bs[s][wn + j * 8 + g][kk + tg + 4], bh1, bl1);
                mma_tf32(c[j], ah, bh0, bh1);     // hi*hi      -> c chain
                mma_tf32(d[j], al, bh0, bh1);     // lo*hi      -> d chain
                mma_tf32(d[j], ah, bl0, bl1);     // hi*lo      -> d chain
            }
        }
    }
    // merge correction accumulator, then write raw partials (bias/relu in k_sens)
    #pragma unroll
    for (int j = 0; j < 4; j++) {
        int n = wn + j * 8 + tg * 2;
        int r0 = block_m + wm + g;
        float2 lo = make_float2(c[j][0] + d[j][0], c[j][1] + d[j][1]);
        float2 hi = make_float2(c[j][2] + d[j][2], c[j][3] + d[j][3]);
        *(float2*)&hp[r0 * 64 + n] = lo;
        *(float2*)&hp[(r0 + 8) * 64 + n] = hi;
    }
}

// ---------------- K3: combine fc1 halves + bias + relu, FC2, input-affine,
//                     sensory synapse sums ----------------
__global__ void k_sens(const float* __restrict__ fc1b,
                       const float* __restrict__ fc2w, const float* __restrict__ fc2b,
                       const float* __restrict__ inw,  const float* __restrict__ inb) {
    __shared__ float ws[64][32];       // ws[o][j] = fc2w[j*64+o]
    __shared__ float sh_h[8][64];
    __shared__ float sh_seq[8][33];
    int tid = threadIdx.x, warp = tid >> 5, lane = tid & 31;
    for (int i = tid; i < 2048; i += 256) ws[i & 63][i >> 6] = fc2w[i];  // coalesced LDG
    int t = blockIdx.x * 8 + warp;
    float h0 = g_hp0[t * 64 + lane]      + g_hp1[t * 64 + lane]      + fc1b[lane];
    float h1 = g_hp0[t * 64 + 32 + lane] + g_hp1[t * 64 + 32 + lane] + fc1b[32 + lane];
    h0 = h0 > 0.f ? h0 : 0.f;          // relu after deterministic combine
    h1 = h1 > 0.f ? h1 : 0.f;
    sh_h[warp][lane] = h0;
    sh_h[warp][32 + lane] = h1;
    __syncthreads();                                  // ws + sh_h visible
    float y0 = fc2b[lane], y1 = 0.f, y2 = 0.f, y3 = 0.f;  // 4-way split chains
    #pragma unroll
    for (int o = 0; o < 64; o += 4) {
        y0 = fmaf(ws[o + 0][lane], sh_h[warp][o + 0], y0);
        y1 = fmaf(ws[o + 1][lane], sh_h[warp][o + 1], y1);
        y2 = fmaf(ws[o + 2][lane], sh_h[warp][o + 2], y2);
        y3 = fmaf(ws[o + 3][lane], sh_h[warp][o + 3], y3);
    }
    float y = (y0 + y1) + (y2 + y3);
    float seq = fmaf(y, inw[lane], inb[lane]);
    sh_seq[warp][lane] = seq;
    __syncwarp();
    if (lane < NSZ) {
        float wn0 = 0.f, wn1 = 0.f, wd0 = 0.f, wd1 = 0.f;   // 2-way split MUFU chains
        #pragma unroll
        for (int s = 0; s < SSZ; s += 2) {
            float arg0 = fmaf(g_sP[s * NSZ + lane], sh_seq[warp][s], g_sQ[s * NSZ + lane]);
            float arg1 = fmaf(g_sP[(s + 1) * NSZ + lane], sh_seq[warp][s + 1],
                              g_sQ[(s + 1) * NSZ + lane]);
            float r0 = fast_rcp(1.0f + fast_ex2(arg0));
            float r1 = fast_rcp(1.0f + fast_ex2(arg1));
            wn0 = fmaf(g_sA[s * NSZ + lane], r0, wn0);
            wd0 = fmaf(g_sW[s * NSZ + lane], r0, wd0);
            wn1 = fmaf(g_sA[(s + 1) * NSZ + lane], r1, wn1);
            wd1 = fmaf(g_sW[(s + 1) * NSZ + lane], r1, wd1);
        }
        g_sens2[t * 32 + lane] = make_float2((wn0 + wn1) + g_gvl[lane], wd0 + wd1);
    }
}

// ---------------- K4: parallel-in-time LTC scan.
// CHUNK=16 outputs/CTA, WARMUP=56 discarded steps (warmup-48 already
// bit-converged at R13; 56 kept for margin). Chunk 0 exact.
__global__ void __launch_bounds__(128, 1)
k_scan(float* __restrict__ out, const float* __restrict__ ow,
       const float* __restrict__ ob) {
    __shared__ float2 s_p[2][4][32];                  // packed (wn, wd) partials
    int tid = threadIdx.x, w = tid >> 5, lane = tid & 31;
    int w1 = (w + 1) & 3, w2 = (w + 2) & 3, w3 = (w + 3) & 3;
    bool act = lane < NSZ;
    float P[5], Q[5], A[5], W[5];
    int srcl[5];
    #pragma unroll
    for (int cc = 0; cc < 5; cc++) {
        int s = w * 5 + cc;
        bool ok = act && (s < NSZ);
        srcl[cc] = s < NSZ ? s : 0;
        P[cc] = ok ? g_rP[s * 32 + lane] : 0.f;
        Q[cc] = ok ? g_rQ[s * 32 + lane] : 0.f;
        A[cc] = ok ? g_rA[s * 32 + lane] : 0.f;
        W[cc] = ok ? g_rW[s * 32 + lane] : 0.f;
    }
    float cmt = act ? g_cmt[lane] : 0.f;
    float cg2 = act ? g_cg2[lane] : 1.f;
    float hA  = act ? g_hA[lane]  : 0.f;
    float ow0 = ow[0], ob0 = ob[0];

    int tbeg = blockIdx.x * CHUNK;
    int t0   = tbeg - WARMUP; if (t0 < 0) t0 = 0;
    int tend = tbeg + CHUNK;

    float v = 0.f;
    float2 sb = g_sens2[t0 * 32 + lane];
    for (int t = t0; t < tend; t++) {
        float2 nx = g_sens2[((t + 1) & (BATCH - 1)) * 32 + lane];
        float wn_base = sb.x + hA;
        float wd_base = sb.y + cg2;
        #pragma unroll
        for (int u = 0; u < UNFOLDS; u++) {
            float vv0 = __shfl_sync(0xffffffffu, v, srcl[0]);
            float vv1 = __shfl_sync(0xffffffffu, v, srcl[1]);
            float vv2 = __shfl_sync(0xffffffffu, v, srcl[2]);
            float vv3 = __shfl_sync(0xffffffffu, v, srcl[3]);
            float vv4 = __shfl_sync(0xffffffffu, v, srcl[4]);
            float t_0 = fast_tanh(fmaf(P[0], vv0, Q[0]));
            float t_1 = fast_tanh(fmaf(P[1], vv1, Q[1]));
            float t_2 = fast_tanh(fmaf(P[2], vv2, Q[2]));
            float t_3 = fast_tanh(fmaf(P[3], vv3, Q[3]));
            float t_4 = fast_tanh(fmaf(P[4], vv4, Q[4]));
            float pn = fmaf(A[4], t_4, fmaf(A[0], t_0, A[2] * t_2) + fmaf(A[1], t_1, A[3] * t_3));
            float pd = fmaf(W[4], t_4, fmaf(W[0], t_0, W[2] * t_2) + fmaf(W[1], t_1, W[3] * t_3));
            s_p[u & 1][w][lane] = make_float2(pn, pd);
            float wn_own = wn_base + pn;
            float wd_own = wd_base + pd;
            __syncthreads();
            float2 o1 = s_p[u & 1][w1][lane];
            float2 o2 = s_p[u & 1][w2][lane];
            float2 o3 = s_p[u & 1][w3][lane];
            float wn = (wn_own + o1.x) + (o2.x + o3.x);
            float wd = (wd_own + o1.y) + (o2.y + o3.y);
            v = fmaf(cmt, v, wn) * fast_rcp(wd);
        }
        if (tid == 96 && t >= tbeg) out[t] = fmaf(v, ow0, ob0);
        sb = nx;
    }
}

// ---------------- launch ----------------
extern "C" void kernel_launch(void* const* d_in, const int* in_sizes, int n_in,
                              void* d_out, int out_size) {
    const float* x        = (const float*)d_in[0];
    const float* conv_w   = (const float*)d_in[1];
    const float* conv_b   = (const float*)d_in[2];
    const float* fc1_w    = (const float*)d_in[3];
    const float* fc1_b    = (const float*)d_in[4];
    const float* fc2_w    = (const float*)d_in[5];
    const float* fc2_b    = (const float*)d_in[6];
    const float* input_w  = (const float*)d_in[7];
    const float* input_b  = (const float*)d_in[8];
    const float* s_w      = (const float*)d_in[9];
    const float* s_mu     = (const float*)d_in[10];
    const float* s_sigma  = (const float*)d_in[11];
    const float* s_erev   = (const float*)d_in[12];
    const float* s_mask   = (const float*)d_in[13];
    const float* w        = (const float*)d_in[14];
    const float* mu       = (const float*)d_in[15];
    const float* sigma    = (const float*)d_in[16];
    const float* erev     = (const float*)d_in[17];
    const float* mask     = (const float*)d_in[18];
    const float* gleak    = (const float*)d_in[19];
    const float* vleak    = (const float*)d_in[20];
    const float* cm       = (const float*)d_in[21];
    const float* output_w = (const float*)d_in[22];
    const float* output_b = (const float*)d_in[23];

    k_prep<<<1, 640>>>(w, mu, sigma, erev, mask, gleak, vleak, cm,
                       s_w, s_mu, s_sigma, s_erev, s_mask);
    k_conv<<<BATCH, 256>>>(x, conv_w, conv_b);
    dim3 fc1_grid(BATCH / 64, 2);
    k_fc1<<<fc1_grid, 256>>>(fc1_w);
    k_sens<<<BATCH / 8, 256>>>(fc1_b, fc2_w, fc2_b, input_w, input_b);
    k_scan<<<NCHUNK, 128>>>((float*)d_out, output_w, output_b);
}